// round 4
// baseline (speedup 1.0000x reference)
#include <cuda_runtime.h>
#include <mma.h>
#include <math.h>

using namespace nvcuda;

#define BATCH  64
#define SEQ    512
#define INSZ   1024
#define HID    1024
#define G4     4096
#define BSH    (BATCH * SEQ * HID)
#define CTAS   128
#define THREADS 256
#define HB     8           // hidden units per CTA
#define NC     32          // gate-columns per CTA (4 gates x 8)
#define SWP    34          // sW row pitch (floats)
#define SPP    34          // sP row pitch (floats)

// Scratch (device globals: allocation-free per harness rules)
__device__ float g_Gx[(size_t)SEQ * BATCH * G4];   // [t][b][4096] = 512 MB
__device__ float g_hbuf[2][BATCH * HID];           // ping-pong running-max h
__device__ unsigned g_bar[SEQ];                    // per-step barrier counters

__global__ void k_init() {
    int i = blockIdx.x * blockDim.x + threadIdx.x;
    if (i < SEQ) g_bar[i] = 0u;
}

// ---------------------------------------------------------------------------
// Phase 1: Gx[t*64 + b][gate*1024 + c] = sum_k x[b,t,k] * Wgate[1024+k][c]
// tf32 wmma, 128x128 tile, BK=32.  (unchanged — known good)
// ---------------------------------------------------------------------------
__global__ __launch_bounds__(256) void k_gemm_x(
    const float* __restrict__ x,
    const float* __restrict__ Wf, const float* __restrict__ Wi,
    const float* __restrict__ Wc, const float* __restrict__ Wo)
{
    __shared__ float sA[128][40];
    __shared__ float sB[32][136];

    const int bn = blockIdx.x;
    const int bm = blockIdx.y;
    const int gate = bn >> 3;
    const int c0 = (bn & 7) * 128;
    const float* W = (gate == 0) ? Wf : (gate == 1) ? Wi : (gate == 2) ? Wc : Wo;

    const int tid  = threadIdx.x;
    const int warp = tid >> 5;
    const int wm   = warp & 3;
    const int wn   = warp >> 2;

    wmma::fragment<wmma::accumulator, 16, 16, 8, float> acc[2][4];
#pragma unroll
    for (int i = 0; i < 2; i++)
#pragma unroll
        for (int j = 0; j < 4; j++) wmma::fill_fragment(acc[i][j], 0.f);

    for (int kc = 0; kc < 32; ++kc) {
#pragma unroll
        for (int l = 0; l < 4; l++) {
            int f = tid + l * 256;
            int r = f >> 3, c4 = f & 7;
            float4 v = *reinterpret_cast<const float4*>(
                x + (size_t)(bm * 128 + r) * 1024 + kc * 32 + c4 * 4);
            sA[r][c4 * 4 + 0] = v.x; sA[r][c4 * 4 + 1] = v.y;
            sA[r][c4 * 4 + 2] = v.z; sA[r][c4 * 4 + 3] = v.w;
        }
#pragma unroll
        for (int l = 0; l < 4; l++) {
            int f = tid + l * 256;
            int kr = f >> 5, c4 = f & 31;
            float4 v = *reinterpret_cast<const float4*>(
                W + (size_t)(1024 + kc * 32 + kr) * 1024 + c0 + c4 * 4);
            sB[kr][c4 * 4 + 0] = v.x; sB[kr][c4 * 4 + 1] = v.y;
            sB[kr][c4 * 4 + 2] = v.z; sB[kr][c4 * 4 + 3] = v.w;
        }
        __syncthreads();

#pragma unroll
        for (int kk = 0; kk < 4; ++kk) {
            wmma::fragment<wmma::matrix_a, 16, 16, 8, wmma::precision::tf32, wmma::row_major> af[2];
            wmma::fragment<wmma::matrix_b, 16, 16, 8, wmma::precision::tf32, wmma::row_major> bfr[4];
#pragma unroll
            for (int i = 0; i < 2; i++) {
                wmma::load_matrix_sync(af[i], &sA[wm * 32 + i * 16][kk * 8], 40);
#pragma unroll
                for (int e = 0; e < af[i].num_elements; e++)
                    af[i].x[e] = wmma::__float_to_tf32(af[i].x[e]);
            }
#pragma unroll
            for (int j = 0; j < 4; j++) {
                wmma::load_matrix_sync(bfr[j], &sB[kk * 8][wn * 64 + j * 16], 136);
#pragma unroll
                for (int e = 0; e < bfr[j].num_elements; e++)
                    bfr[j].x[e] = wmma::__float_to_tf32(bfr[j].x[e]);
            }
#pragma unroll
            for (int i = 0; i < 2; i++)
#pragma unroll
                for (int j = 0; j < 4; j++)
                    wmma::mma_sync(acc[i][j], af[i], bfr[j], acc[i][j]);
        }
        __syncthreads();
    }

#pragma unroll
    for (int i = 0; i < 2; i++) {
        int m0 = bm * 128 + wm * 32 + i * 16;
        int bidx = m0 >> 9;
        int t0 = m0 & 511;
        float* rowbase = g_Gx + (size_t)(t0 * 64 + bidx) * G4 + gate * 1024 + c0 + wn * 64;
#pragma unroll
        for (int j = 0; j < 4; j++)
            wmma::store_matrix_sync(rowbase + j * 16, acc[i][j],
                                    (unsigned)(64 * G4), wmma::mem_row_major);
    }
}

// ---------------------------------------------------------------------------
// Phase 2: persistent kernel, 128 CTAs x 256 thr, 1 CTA/SM.
// CTA owns 32 gate-columns; W pre-converted to tf32 in SMEM (resident).
// Per step: 8-warp K-split GEMM with A fragments loaded DIRECTLY from global
// (L2 broadcast; no smem staging, no intra-GEMM syncs). One sync before the
// partial reduction. Grid barrier includes reader-side __threadfence()
// (gpu-scope => CCTL.IVALL) so plain global loads of h are coherent.
// ---------------------------------------------------------------------------
__device__ __forceinline__ float sigf(float v) { return 1.f / (1.f + expf(-v)); }

__global__ __launch_bounds__(THREADS, 1) void k_lstm(
    const float* __restrict__ Wf, const float* __restrict__ Wi,
    const float* __restrict__ Wc, const float* __restrict__ Wo,
    const float* __restrict__ bfv, const float* __restrict__ biv,
    const float* __restrict__ bcv, const float* __restrict__ bov,
    float* __restrict__ out)
{
    extern __shared__ float smem[];
    float* sW = smem;                  // [1024][SWP]  tf32-preconverted weights
    float* sP = smem + 1024 * SWP;     // [8][64][SPP] per-warp partials

    __shared__ float sBias[NC];

    const int tid  = threadIdx.x;
    const int warp = tid >> 5;         // 8 warps, K-split (128 k each)
    const int h0   = blockIdx.x * HB;

    // ---- one-time: preload + pre-round this CTA's 32 weight columns ----
    for (int k = tid; k < 1024; k += THREADS) {
#pragma unroll
        for (int g = 0; g < 4; g++) {
            const float* W = (g == 0) ? Wf : (g == 1) ? Wi : (g == 2) ? Wc : Wo;
            float4 v0 = *reinterpret_cast<const float4*>(W + (size_t)k * 1024 + h0);
            float4 v1 = *reinterpret_cast<const float4*>(W + (size_t)k * 1024 + h0 + 4);
            float* d = &sW[k * SWP + g * 8];
            d[0] = wmma::__float_to_tf32(v0.x); d[1] = wmma::__float_to_tf32(v0.y);
            d[2] = wmma::__float_to_tf32(v0.z); d[3] = wmma::__float_to_tf32(v0.w);
            d[4] = wmma::__float_to_tf32(v1.x); d[5] = wmma::__float_to_tf32(v1.y);
            d[6] = wmma::__float_to_tf32(v1.z); d[7] = wmma::__float_to_tf32(v1.w);
        }
    }
    if (tid < NC) {
        int g = tid >> 3, hh = tid & 7;
        const float* bv = (g == 0) ? bfv : (g == 1) ? biv : (g == 2) ? bcv : bov;
        sBias[tid] = bv[h0 + hh];
    }
    __syncthreads();

    // persistent per-thread state: elems e = tid, tid+256 of (64 b x 8 hh)
    float creg[2] = {0.f, 0.f};
    float hreg[2] = {0.f, 0.f};

    for (int t = 0; t < SEQ; ++t) {
        // ---- prefetch this step's Gx gate slice (independent of h) ----
        float gx[2][4];
#pragma unroll
        for (int l = 0; l < 2; l++) {
            int e = tid + l * THREADS;
            int b = e >> 3, hh = e & 7;
            const float* gp = g_Gx + (size_t)(t * 64 + b) * G4 + h0 + hh;
#pragma unroll
            for (int g = 0; g < 4; g++)
                gx[l][g] = __ldcg(gp + g * 1024);
        }

        // ---- recurrent GEMM: h_in(64x1024) @ sW(1024x32), K-split x8 ----
        if (t > 0) {
            const float* __restrict__ hin = g_hbuf[(t + 1) & 1];
            const float* hrow0 = hin;                  // rows 0,16,32,48 via ldm
            const int kbase = warp * 128;

            wmma::fragment<wmma::accumulator, 16, 16, 8, float> acc[4][2];
#pragma unroll
            for (int i = 0; i < 4; i++) {
                wmma::fill_fragment(acc[i][0], 0.f);
                wmma::fill_fragment(acc[i][1], 0.f);
            }

#pragma unroll 4
            for (int kk = 0; kk < 16; ++kk) {
                const int k0 = kbase + kk * 8;
                wmma::fragment<wmma::matrix_b, 16, 16, 8, wmma::precision::tf32, wmma::row_major> bfr[2];
                wmma::load_matrix_sync(bfr[0], &sW[k0 * SWP], SWP);       // pre-rounded
                wmma::load_matrix_sync(bfr[1], &sW[k0 * SWP + 16], SWP);

                wmma::fragment<wmma::matrix_a, 16, 16, 8, wmma::precision::tf32, wmma::row_major> af[4];
#pragma unroll
                for (int i = 0; i < 4; i++) {
                    wmma::load_matrix_sync(af[i], hrow0 + (size_t)(i * 16) * 1024 + k0, 1024);
#pragma unroll
                    for (int e = 0; e < af[i].num_elements; e++)
                        af[i].x[e] = wmma::__float_to_tf32(af[i].x[e]);
                    wmma::mma_sync(acc[i][0], af[i], bfr[0], acc[i][0]);
                    wmma::mma_sync(acc[i][1], af[i], bfr[1], acc[i][1]);
                }
            }

            // per-warp partials -> smem, single sync
#pragma unroll
            for (int i = 0; i < 4; i++)
#pragma unroll
                for (int j = 0; j < 2; j++)
                    wmma::store_matrix_sync(&sP[warp * (64 * SPP) + (i * 16) * SPP + j * 16],
                                            acc[i][j], SPP, wmma::mem_row_major);
            __syncthreads();
        }

        // ---- elementwise: reduce partials, gates, state, cummax, outputs ----
        float* __restrict__ hnew = g_hbuf[t & 1];
#pragma unroll
        for (int l = 0; l < 2; l++) {
            int e  = tid + l * THREADS;      // 0..511
            int b  = e >> 3, hh = e & 7;
            int h  = h0 + hh;

            float s0 = 0.f, s1 = 0.f, s2 = 0.f, s3 = 0.f;
            if (t > 0) {
#pragma unroll
                for (int w = 0; w < 8; w++) {
                    const float* p = &sP[w * (64 * SPP) + b * SPP];
                    s0 += p[hh];
                    s1 += p[8 + hh];
                    s2 += p[16 + hh];
                    s3 += p[24 + hh];
                }
            }
            float gf = s0 + gx[l][0] + sBias[hh];
            float gi = s1 + gx[l][1] + sBias[8 + hh];
            float gc = s2 + gx[l][2] + sBias[16 + hh];
            float go = s3 + gx[l][3] + sBias[24 + hh];

            float Cn = sigf(gf) * creg[l] + sigf(gi) * tanhf(gc);
            creg[l] = Cn;
            float hv = sigf(go) * tanhf(Cn);

            out[(size_t)b * SEQ * HID + (size_t)t * HID + h] = hv;

            float hm = (t == 0) ? hv : fmaxf(hreg[l], hv);
            hreg[l] = hm;
            hnew[b * HID + h] = hm;

            if (t == SEQ - 1) {
                out[(size_t)BSH + b * HID + h] = hm;                     // h_fin
                out[(size_t)BSH + BATCH * HID + b * HID + h] = Cn;       // C_fin
            }
        }

        // ---- grid barrier: release h writes, acquire (+L1 IVALL) for t+1 ----
        if (t < SEQ - 1) {
            __threadfence();                 // release this thread's h stores
            __syncthreads();
            if (tid == 0) {
                atomicAdd(&g_bar[t], 1u);
                volatile unsigned* p = &g_bar[t];
                while (*p < (unsigned)CTAS) __nanosleep(32);
                __threadfence();             // acquire: gpu-scope fence => CCTL.IVALL
            }
            __syncthreads();
        }
    }
}

extern "C" void kernel_launch(void* const* d_in, const int* in_sizes, int n_in,
                              void* d_out, int out_size) {
    const float* x  = (const float*)d_in[0];
    const float* Wf = (const float*)d_in[1];
    const float* bf = (const float*)d_in[2];
    const float* Wi = (const float*)d_in[3];
    const float* bi = (const float*)d_in[4];
    const float* Wc = (const float*)d_in[5];
    const float* bc = (const float*)d_in[6];
    const float* Wo = (const float*)d_in[7];
    const float* bo = (const float*)d_in[8];
    float* out = (float*)d_out;

    static const size_t SMEM = (1024 * SWP + 8 * 64 * SPP) * sizeof(float); // 208896 B
    cudaFuncSetAttribute(k_lstm, cudaFuncAttributeMaxDynamicSharedMemorySize, (int)SMEM);

    k_init<<<1, 512>>>();
    k_gemm_x<<<dim3(32, 256), 256>>>(x, Wf, Wi, Wc, Wo);
    k_lstm<<<CTAS, THREADS, SMEM>>>(Wf, Wi, Wc, Wo, bf, bi, bc, bo, out);
}

// round 5
// speedup vs baseline: 1.3867x; 1.3867x over previous
#include <cuda_runtime.h>
#include <mma.h>
#include <math.h>

using namespace nvcuda;

#define BATCH  64
#define SEQ    512
#define INSZ   1024
#define HID    1024
#define G4     4096
#define BSH    (BATCH * SEQ * HID)
#define CTAS   128
#define THREADS 256
#define HB     8           // hidden units per CTA
#define NC     32          // gate-columns per CTA (4 gates x 8)
#define SWP    34          // sW row pitch (floats)
#define SPP    34          // sP row pitch (floats)
#define ACP    33          // sAcc row pitch (floats)
#define TD     16          // dense warmup steps

// Scratch (device globals: allocation-free per harness rules)
__device__ float g_Gx[(size_t)SEQ * BATCH * G4];   // [t][b][4096] = 512 MB
__device__ float g_hbuf[2][BATCH * HID];           // ping-pong running-max h (dense steps)
__device__ unsigned g_bar[SEQ];                    // per-step barrier counters
__device__ float2 g_blist[3][BATCH][HID];          // triple-buffered per-b update lists
__device__ int    g_lcnt[3][BATCH];                // list counters

__global__ void k_init() {
    int i = blockIdx.x * blockDim.x + threadIdx.x;
    if (i < SEQ) g_bar[i] = 0u;
    if (i < 3 * BATCH) (&g_lcnt[0][0])[i] = 0;
}

// ---------------------------------------------------------------------------
// Phase 1: Gx[t*64 + b][gate*1024 + c] = sum_k x[b,t,k] * Wgate[1024+k][c]
// tf32 wmma, 128x128 tile, BK=32.  (unchanged — known good)
// ---------------------------------------------------------------------------
__global__ __launch_bounds__(256) void k_gemm_x(
    const float* __restrict__ x,
    const float* __restrict__ Wf, const float* __restrict__ Wi,
    const float* __restrict__ Wc, const float* __restrict__ Wo)
{
    __shared__ float sA[128][40];
    __shared__ float sB[32][136];

    const int bn = blockIdx.x;
    const int bm = blockIdx.y;
    const int gate = bn >> 3;
    const int c0 = (bn & 7) * 128;
    const float* W = (gate == 0) ? Wf : (gate == 1) ? Wi : (gate == 2) ? Wc : Wo;

    const int tid  = threadIdx.x;
    const int warp = tid >> 5;
    const int wm   = warp & 3;
    const int wn   = warp >> 2;

    wmma::fragment<wmma::accumulator, 16, 16, 8, float> acc[2][4];
#pragma unroll
    for (int i = 0; i < 2; i++)
#pragma unroll
        for (int j = 0; j < 4; j++) wmma::fill_fragment(acc[i][j], 0.f);

    for (int kc = 0; kc < 32; ++kc) {
#pragma unroll
        for (int l = 0; l < 4; l++) {
            int f = tid + l * 256;
            int r = f >> 3, c4 = f & 7;
            float4 v = *reinterpret_cast<const float4*>(
                x + (size_t)(bm * 128 + r) * 1024 + kc * 32 + c4 * 4);
            sA[r][c4 * 4 + 0] = v.x; sA[r][c4 * 4 + 1] = v.y;
            sA[r][c4 * 4 + 2] = v.z; sA[r][c4 * 4 + 3] = v.w;
        }
#pragma unroll
        for (int l = 0; l < 4; l++) {
            int f = tid + l * 256;
            int kr = f >> 5, c4 = f & 31;
            float4 v = *reinterpret_cast<const float4*>(
                W + (size_t)(1024 + kc * 32 + kr) * 1024 + c0 + c4 * 4);
            sB[kr][c4 * 4 + 0] = v.x; sB[kr][c4 * 4 + 1] = v.y;
            sB[kr][c4 * 4 + 2] = v.z; sB[kr][c4 * 4 + 3] = v.w;
        }
        __syncthreads();

#pragma unroll
        for (int kk = 0; kk < 4; ++kk) {
            wmma::fragment<wmma::matrix_a, 16, 16, 8, wmma::precision::tf32, wmma::row_major> af[2];
            wmma::fragment<wmma::matrix_b, 16, 16, 8, wmma::precision::tf32, wmma::row_major> bfr[4];
#pragma unroll
            for (int i = 0; i < 2; i++) {
                wmma::load_matrix_sync(af[i], &sA[wm * 32 + i * 16][kk * 8], 40);
#pragma unroll
                for (int e = 0; e < af[i].num_elements; e++)
                    af[i].x[e] = wmma::__float_to_tf32(af[i].x[e]);
            }
#pragma unroll
            for (int j = 0; j < 4; j++) {
                wmma::load_matrix_sync(bfr[j], &sB[kk * 8][wn * 64 + j * 16], 136);
#pragma unroll
                for (int e = 0; e < bfr[j].num_elements; e++)
                    bfr[j].x[e] = wmma::__float_to_tf32(bfr[j].x[e]);
            }
#pragma unroll
            for (int i = 0; i < 2; i++)
#pragma unroll
                for (int j = 0; j < 4; j++)
                    wmma::mma_sync(acc[i][j], af[i], bfr[j], acc[i][j]);
        }
        __syncthreads();
    }

#pragma unroll
    for (int i = 0; i < 2; i++) {
        int m0 = bm * 128 + wm * 32 + i * 16;
        int bidx = m0 >> 9;
        int t0 = m0 & 511;
        float* rowbase = g_Gx + (size_t)(t0 * 64 + bidx) * G4 + gate * 1024 + c0 + wn * 64;
#pragma unroll
        for (int j = 0; j < 4; j++)
            wmma::store_matrix_sync(rowbase + j * 16, acc[i][j],
                                    (unsigned)(64 * G4), wmma::mem_row_major);
    }
}

// ---------------------------------------------------------------------------
// Phase 2: persistent kernel. CTA owns 32 gate-columns; sW resident in SMEM.
// t < TD: dense tf32 GEMM of Wh @ hmax (last dense step seeds sAcc baseline).
// t >= TD: incremental sparse rank-1 updates from cummax record events:
//   g_acc += sum_records delta * sW[k,:]   (exact telescoping, fp32)
// Per-b update lists triple-buffered; counters reset in 3-phase rotation.
// ---------------------------------------------------------------------------
__device__ __forceinline__ float sigf(float v) { return 1.f / (1.f + expf(-v)); }

__global__ __launch_bounds__(THREADS, 1) void k_lstm(
    const float* __restrict__ Wf, const float* __restrict__ Wi,
    const float* __restrict__ Wc, const float* __restrict__ Wo,
    const float* __restrict__ bfv, const float* __restrict__ biv,
    const float* __restrict__ bcv, const float* __restrict__ bov,
    float* __restrict__ out)
{
    extern __shared__ float smem[];
    float* sW   = smem;                         // [1024][SWP] tf32-rounded weights
    float* sP   = smem + 1024 * SWP;            // [8][64][SPP] dense partials
    float* sAcc = sP + 8 * 64 * SPP;            // [64][ACP] recurrent accumulator

    __shared__ float sBias[NC];

    const int tid  = threadIdx.x;
    const int warp = tid >> 5;
    const int lane = tid & 31;
    const int h0   = blockIdx.x * HB;

    // ---- one-time: preload + pre-round this CTA's 32 weight columns ----
    for (int k = tid; k < 1024; k += THREADS) {
#pragma unroll
        for (int g = 0; g < 4; g++) {
            const float* W = (g == 0) ? Wf : (g == 1) ? Wi : (g == 2) ? Wc : Wo;
            float4 v0 = *reinterpret_cast<const float4*>(W + (size_t)k * 1024 + h0);
            float4 v1 = *reinterpret_cast<const float4*>(W + (size_t)k * 1024 + h0 + 4);
            float* d = &sW[k * SWP + g * 8];
            // NOTE: keep full fp32 here; tf32 rounding only happens inside the
            // dense wmma path via fragment conversion of A (B pre-rounded there
            // was an optimization; for sparse updates we want full precision).
            d[0] = v0.x; d[1] = v0.y; d[2] = v0.z; d[3] = v0.w;
            d[4] = v1.x; d[5] = v1.y; d[6] = v1.z; d[7] = v1.w;
        }
    }
    if (tid < NC) {
        int g = tid >> 3, hh = tid & 7;
        const float* bv = (g == 0) ? bfv : (g == 1) ? biv : (g == 2) ? bcv : bov;
        sBias[tid] = bv[h0 + hh];
    }
    __syncthreads();

    // persistent per-thread state: elems e = tid, tid+256 of (64 b x 8 hh)
    float creg[2] = {0.f, 0.f};
    float hreg[2] = {0.f, 0.f};

    for (int t = 0; t < SEQ; ++t) {
        // ---- rotate-reset list counters for phase (t+1)%3 ----
        if (blockIdx.x < BATCH && tid == 0)
            g_lcnt[(t + 1) % 3][blockIdx.x] = 0;

        // ---- prefetch this step's Gx gate slice (independent of recurrence) --
        float gx[2][4];
#pragma unroll
        for (int l = 0; l < 2; l++) {
            int e = tid + l * THREADS;
            int b = e >> 3, hh = e & 7;
            const float* gp = g_Gx + (size_t)(t * 64 + b) * G4 + h0 + hh;
#pragma unroll
            for (int g = 0; g < 4; g++)
                gx[l][g] = __ldcg(gp + g * 1024);
        }

        const bool dense = (t < TD);

        if (t > 0) {
            if (dense) {
                // ---- dense recurrent GEMM (R4 path): K-split x8, A from global
                const float* __restrict__ hin = g_hbuf[(t + 1) & 1];
                const int kbase = warp * 128;

                wmma::fragment<wmma::accumulator, 16, 16, 8, float> acc[4][2];
#pragma unroll
                for (int i = 0; i < 4; i++) {
                    wmma::fill_fragment(acc[i][0], 0.f);
                    wmma::fill_fragment(acc[i][1], 0.f);
                }
#pragma unroll 4
                for (int kk = 0; kk < 16; ++kk) {
                    const int k0 = kbase + kk * 8;
                    wmma::fragment<wmma::matrix_b, 16, 16, 8, wmma::precision::tf32, wmma::row_major> bfr[2];
                    wmma::load_matrix_sync(bfr[0], &sW[k0 * SWP], SWP);
                    wmma::load_matrix_sync(bfr[1], &sW[k0 * SWP + 16], SWP);
#pragma unroll
                    for (int e = 0; e < bfr[0].num_elements; e++) {
                        bfr[0].x[e] = wmma::__float_to_tf32(bfr[0].x[e]);
                        bfr[1].x[e] = wmma::__float_to_tf32(bfr[1].x[e]);
                    }
                    wmma::fragment<wmma::matrix_a, 16, 16, 8, wmma::precision::tf32, wmma::row_major> af[4];
#pragma unroll
                    for (int i = 0; i < 4; i++) {
                        wmma::load_matrix_sync(af[i], hin + (size_t)(i * 16) * 1024 + k0, 1024);
#pragma unroll
                        for (int e = 0; e < af[i].num_elements; e++)
                            af[i].x[e] = wmma::__float_to_tf32(af[i].x[e]);
                        wmma::mma_sync(acc[i][0], af[i], bfr[0], acc[i][0]);
                        wmma::mma_sync(acc[i][1], af[i], bfr[1], acc[i][1]);
                    }
                }
#pragma unroll
                for (int i = 0; i < 4; i++)
#pragma unroll
                    for (int j = 0; j < 2; j++)
                        wmma::store_matrix_sync(&sP[warp * (64 * SPP) + (i * 16) * SPP + j * 16],
                                                acc[i][j], SPP, wmma::mem_row_major);
                __syncthreads();
            } else {
                // ---- sparse apply: warp w owns b in [8w, 8w+8) ----
                const int ph = (t - 1) % 3;
#pragma unroll 1
                for (int bb = 0; bb < 8; ++bb) {
                    const int b = warp * 8 + bb;
                    const int n = __ldcg(&g_lcnt[ph][b]);
                    const float2* __restrict__ lst = &g_blist[ph][b][0];
                    float a0 = sAcc[b * ACP + lane];
                    float a1 = 0.f;
                    int e = 0;
                    for (; e + 1 < n; e += 2) {
                        float2 e0 = __ldcg(&lst[e]);
                        float2 e1 = __ldcg(&lst[e + 1]);
                        a0 += e0.y * sW[__float_as_int(e0.x) * SWP + lane];
                        a1 += e1.y * sW[__float_as_int(e1.x) * SWP + lane];
                    }
                    if (e < n) {
                        float2 e0 = __ldcg(&lst[e]);
                        a0 += e0.y * sW[__float_as_int(e0.x) * SWP + lane];
                    }
                    sAcc[b * ACP + lane] = a0 + a1;
                }
                __syncthreads();
            }
        }

        // ---- elementwise: gates, state, cummax, emissions, outputs ----
        float* __restrict__ hnew = g_hbuf[t & 1];
#pragma unroll
        for (int l = 0; l < 2; l++) {
            int e  = tid + l * THREADS;      // 0..511
            int b  = e >> 3, hh = e & 7;
            int h  = h0 + hh;

            float s0, s1, s2, s3;
            if (dense) {
                s0 = s1 = s2 = s3 = 0.f;
                if (t > 0) {
#pragma unroll
                    for (int w = 0; w < 8; w++) {
                        const float* p = &sP[w * (64 * SPP) + b * SPP];
                        s0 += p[hh];
                        s1 += p[8 + hh];
                        s2 += p[16 + hh];
                        s3 += p[24 + hh];
                    }
                }
                // seed / refresh the accumulator baseline
                sAcc[b * ACP + hh]      = s0;
                sAcc[b * ACP + 8 + hh]  = s1;
                sAcc[b * ACP + 16 + hh] = s2;
                sAcc[b * ACP + 24 + hh] = s3;
            } else {
                s0 = sAcc[b * ACP + hh];
                s1 = sAcc[b * ACP + 8 + hh];
                s2 = sAcc[b * ACP + 16 + hh];
                s3 = sAcc[b * ACP + 24 + hh];
            }

            float gf = s0 + gx[l][0] + sBias[hh];
            float gi = s1 + gx[l][1] + sBias[8 + hh];
            float gc = s2 + gx[l][2] + sBias[16 + hh];
            float go = s3 + gx[l][3] + sBias[24 + hh];

            float Cn = sigf(gf) * creg[l] + sigf(gi) * tanhf(gc);
            creg[l] = Cn;
            float hv = sigf(go) * tanhf(Cn);

            out[(size_t)b * SEQ * HID + (size_t)t * HID + h] = hv;

            bool newmax = (t == 0) || (hv > hreg[l]);
            float hm = (t == 0) ? hv : fmaxf(hreg[l], hv);

            // emit record event for the sparse accumulator (consumed at t+1)
            if (t >= TD - 1 && t < SEQ - 1 && hv > hreg[l]) {
                float dlt = hv - hreg[l];
                int pos = atomicAdd(&g_lcnt[t % 3][b], 1);
                g_blist[t % 3][b][pos] = make_float2(__int_as_float(h), dlt);
            }
            (void)newmax;
            hreg[l] = hm;

            // hmax buffer only needed by dense steps (reads at t+1 <= TD-1)
            if (t < TD - 1) hnew[b * HID + h] = hm;

            if (t == SEQ - 1) {
                out[(size_t)BSH + b * HID + h] = hm;                     // h_fin
                out[(size_t)BSH + BATCH * HID + b * HID + h] = Cn;       // C_fin
            }
        }

        // ---- grid barrier: release stores, acquire (+L1 IVALL) for t+1 ----
        if (t < SEQ - 1) {
            __threadfence();
            __syncthreads();
            if (tid == 0) {
                atomicAdd(&g_bar[t], 1u);
                volatile unsigned* p = &g_bar[t];
                while (*p < (unsigned)CTAS) __nanosleep(32);
                __threadfence();             // gpu-scope => CCTL.IVALL (L1 coherence)
            }
            __syncthreads();
        }
    }
}

extern "C" void kernel_launch(void* const* d_in, const int* in_sizes, int n_in,
                              void* d_out, int out_size) {
    const float* x  = (const float*)d_in[0];
    const float* Wf = (const float*)d_in[1];
    const float* bf = (const float*)d_in[2];
    const float* Wi = (const float*)d_in[3];
    const float* bi = (const float*)d_in[4];
    const float* Wc = (const float*)d_in[5];
    const float* bc = (const float*)d_in[6];
    const float* Wo = (const float*)d_in[7];
    const float* bo = (const float*)d_in[8];
    float* out = (float*)d_out;

    static const size_t SMEM =
        (1024 * SWP + 8 * 64 * SPP + 64 * ACP) * sizeof(float);  // 217,344 B
    cudaFuncSetAttribute(k_lstm, cudaFuncAttributeMaxDynamicSharedMemorySize, (int)SMEM);

    k_init<<<1, 512>>>();
    k_gemm_x<<<dim3(32, 256), 256>>>(x, Wf, Wi, Wc, Wo);
    k_lstm<<<CTAS, THREADS, SMEM>>>(Wf, Wi, Wc, Wo, bf, bi, bc, bo, out);
}

// round 6
// speedup vs baseline: 1.5597x; 1.1248x over previous
#include <cuda_runtime.h>
#include <cuda_pipeline.h>
#include <mma.h>
#include <math.h>

using namespace nvcuda;

#define BATCH  64
#define SEQ    512
#define INSZ   1024
#define HID    1024
#define G4     4096
#define BSH    (BATCH * SEQ * HID)
#define CTAS   128
#define THREADS 256
#define HB     8           // hidden units per CTA
#define NC     32          // gate-columns per CTA (4 gates x 8)
#define SWP    34          // sW row pitch (floats)
#define SPP    34          // sP row pitch (floats)
#define ACP    33          // sAcc row pitch (floats)
#define TD     16          // dense warmup steps
#define SAP    36          // gemm sA pitch
#define SBP    132         // gemm sB pitch

// Scratch (device globals: allocation-free per harness rules)
__device__ float g_Gx[(size_t)SEQ * BATCH * G4];   // [t][b][4096] = 512 MB
__device__ float g_hbuf[2][BATCH * HID];           // ping-pong hmax (dense steps only)
__device__ unsigned g_bar[SEQ];                    // per-step barrier counters
__device__ float2 g_blist[3][BATCH][HID];          // triple-buffered per-b update lists
__device__ int    g_lcnt[3][BATCH];                // list counters

__global__ void k_init() {
    int i = blockIdx.x * blockDim.x + threadIdx.x;
    if (i < SEQ) g_bar[i] = 0u;
    if (i < 3 * BATCH) (&g_lcnt[0][0])[i] = 0;
}

// ---------------------------------------------------------------------------
// Phase 1: Gx = X @ Wx (4 gates), tf32 wmma 128x128 tile, BK=32,
// 2-stage cp.async double buffering.
// ---------------------------------------------------------------------------
__global__ __launch_bounds__(256) void k_gemm_x(
    const float* __restrict__ x,
    const float* __restrict__ Wf, const float* __restrict__ Wi,
    const float* __restrict__ Wc, const float* __restrict__ Wo)
{
    extern __shared__ float dsm[];
    float (*sA)[128][SAP] = (float(*)[128][SAP])dsm;                    // 2 stages
    float (*sB)[32][SBP]  = (float(*)[32][SBP])(dsm + 2 * 128 * SAP);

    const int bn = blockIdx.x;
    const int bm = blockIdx.y;
    const int gate = bn >> 3;
    const int c0 = (bn & 7) * 128;
    const float* W = (gate == 0) ? Wf : (gate == 1) ? Wi : (gate == 2) ? Wc : Wo;

    const int tid  = threadIdx.x;
    const int warp = tid >> 5;
    const int wm   = warp & 3;
    const int wn   = warp >> 2;

    // per-thread fixed copy slots
    const int ar = tid >> 1, ac4 = (tid & 1) * 4;          // A: 2 thr/row? no: below
    (void)ar; (void)ac4;

    auto issue = [&](int stage, int kc) {
        // A tile: 128x32 floats = 1024 float4; 256 thr x 4
#pragma unroll
        for (int l = 0; l < 4; l++) {
            int f = tid + l * 256;
            int r = f >> 3, c4 = f & 7;
            __pipeline_memcpy_async(&sA[stage][r][c4 * 4],
                x + (size_t)(bm * 128 + r) * 1024 + kc * 32 + c4 * 4, 16);
        }
        // B tile: 32x128 floats = 1024 float4
#pragma unroll
        for (int l = 0; l < 4; l++) {
            int f = tid + l * 256;
            int kr = f >> 5, c4 = f & 31;
            __pipeline_memcpy_async(&sB[stage][kr][c4 * 4],
                W + (size_t)(1024 + kc * 32 + kr) * 1024 + c0 + c4 * 4, 16);
        }
        __pipeline_commit();
    };

    wmma::fragment<wmma::accumulator, 16, 16, 8, float> acc[2][4];
#pragma unroll
    for (int i = 0; i < 2; i++)
#pragma unroll
        for (int j = 0; j < 4; j++) wmma::fill_fragment(acc[i][j], 0.f);

    issue(0, 0);
    for (int kc = 0; kc < 32; ++kc) {
        if (kc + 1 < 32) {
            issue((kc + 1) & 1, kc + 1);
            __pipeline_wait_prior(1);
        } else {
            __pipeline_wait_prior(0);
        }
        __syncthreads();

        const int st = kc & 1;
#pragma unroll
        for (int kk = 0; kk < 4; ++kk) {
            wmma::fragment<wmma::matrix_a, 16, 16, 8, wmma::precision::tf32, wmma::row_major> af[2];
            wmma::fragment<wmma::matrix_b, 16, 16, 8, wmma::precision::tf32, wmma::row_major> bfr[4];
#pragma unroll
            for (int i = 0; i < 2; i++) {
                wmma::load_matrix_sync(af[i], &sA[st][wm * 32 + i * 16][kk * 8], SAP);
#pragma unroll
                for (int e = 0; e < af[i].num_elements; e++)
                    af[i].x[e] = wmma::__float_to_tf32(af[i].x[e]);
            }
#pragma unroll
            for (int j = 0; j < 4; j++) {
                wmma::load_matrix_sync(bfr[j], &sB[st][kk * 8][wn * 64 + j * 16], SBP);
#pragma unroll
                for (int e = 0; e < bfr[j].num_elements; e++)
                    bfr[j].x[e] = wmma::__float_to_tf32(bfr[j].x[e]);
            }
#pragma unroll
            for (int i = 0; i < 2; i++)
#pragma unroll
                for (int j = 0; j < 4; j++)
                    wmma::mma_sync(acc[i][j], af[i], bfr[j], acc[i][j]);
        }
        __syncthreads();
    }

#pragma unroll
    for (int i = 0; i < 2; i++) {
        int m0 = bm * 128 + wm * 32 + i * 16;
        int bidx = m0 >> 9;
        int t0 = m0 & 511;
        float* rowbase = g_Gx + (size_t)(t0 * 64 + bidx) * G4 + gate * 1024 + c0 + wn * 64;
#pragma unroll
        for (int j = 0; j < 4; j++)
            wmma::store_matrix_sync(rowbase + j * 16, acc[i][j],
                                    (unsigned)(64 * G4), wmma::mem_row_major);
    }
}

// ---------------------------------------------------------------------------
// Phase 2: persistent kernel. Dense tf32 warmup (t<TD) seeds the fp32
// accumulator; afterwards exact sparse rank-1 cummax-record updates.
// Latency-optimized: parallel counter/list loads, work hidden under barrier.
// ---------------------------------------------------------------------------
__device__ __forceinline__ float sigf(float v) { return 1.f / (1.f + expf(-v)); }

__global__ __launch_bounds__(THREADS, 1) void k_lstm(
    const float* __restrict__ Wf, const float* __restrict__ Wi,
    const float* __restrict__ Wc, const float* __restrict__ Wo,
    const float* __restrict__ bfv, const float* __restrict__ biv,
    const float* __restrict__ bcv, const float* __restrict__ bov,
    float* __restrict__ out)
{
    extern __shared__ float smem[];
    float* sW   = smem;                         // [1024][SWP] fp32 weights (resident)
    float* sP   = smem + 1024 * SWP;            // [8][64][SPP] dense partials
    float* sAcc = sP + 8 * 64 * SPP;            // [64][ACP] recurrent accumulator

    __shared__ float sBias[NC];

    const int tid  = threadIdx.x;
    const int warp = tid >> 5;
    const int lane = tid & 31;
    const int h0   = blockIdx.x * HB;

    // ---- one-time: preload this CTA's 32 weight columns (fp32) ----
    for (int k = tid; k < 1024; k += THREADS) {
#pragma unroll
        for (int g = 0; g < 4; g++) {
            const float* W = (g == 0) ? Wf : (g == 1) ? Wi : (g == 2) ? Wc : Wo;
            float4 v0 = *reinterpret_cast<const float4*>(W + (size_t)k * 1024 + h0);
            float4 v1 = *reinterpret_cast<const float4*>(W + (size_t)k * 1024 + h0 + 4);
            float* d = &sW[k * SWP + g * 8];
            d[0] = v0.x; d[1] = v0.y; d[2] = v0.z; d[3] = v0.w;
            d[4] = v1.x; d[5] = v1.y; d[6] = v1.z; d[7] = v1.w;
        }
    }
    if (tid < NC) {
        int g = tid >> 3, hh = tid & 7;
        const float* bv = (g == 0) ? bfv : (g == 1) ? biv : (g == 2) ? bcv : bov;
        sBias[tid] = bv[h0 + hh];
    }
    __syncthreads();

    // persistent per-thread state
    float creg[2] = {0.f, 0.f};
    float hreg[2] = {0.f, 0.f};

    // software-pipelined Gx prefetch
    float gx[2][4];
#pragma unroll
    for (int l = 0; l < 2; l++) {
        int e = tid + l * THREADS;
        int b = e >> 3, hh = e & 7;
        const float* gp = g_Gx + (size_t)b * G4 + h0 + hh;   // t = 0
#pragma unroll
        for (int g = 0; g < 4; g++) gx[l][g] = __ldcg(gp + g * 1024);
    }

    for (int t = 0; t < SEQ; ++t) {
        // reset counter for phase (t+1)%3 (dead phase; atomic -> L2, no fence)
        if (blockIdx.x < BATCH && tid == 0)
            atomicExch(&g_lcnt[(t + 1) % 3][blockIdx.x], 0);

        const bool dense = (t < TD);

        if (t > 0) {
            if (dense) {
                // ---- dense recurrent GEMM: K-split x8, A from global ----
                const float* __restrict__ hin = g_hbuf[(t + 1) & 1];
                const int kbase = warp * 128;

                wmma::fragment<wmma::accumulator, 16, 16, 8, float> acc[4][2];
#pragma unroll
                for (int i = 0; i < 4; i++) {
                    wmma::fill_fragment(acc[i][0], 0.f);
                    wmma::fill_fragment(acc[i][1], 0.f);
                }
#pragma unroll 4
                for (int kk = 0; kk < 16; ++kk) {
                    const int k0 = kbase + kk * 8;
                    wmma::fragment<wmma::matrix_b, 16, 16, 8, wmma::precision::tf32, wmma::row_major> bfr[2];
                    wmma::load_matrix_sync(bfr[0], &sW[k0 * SWP], SWP);
                    wmma::load_matrix_sync(bfr[1], &sW[k0 * SWP + 16], SWP);
#pragma unroll
                    for (int e = 0; e < bfr[0].num_elements; e++) {
                        bfr[0].x[e] = wmma::__float_to_tf32(bfr[0].x[e]);
                        bfr[1].x[e] = wmma::__float_to_tf32(bfr[1].x[e]);
                    }
                    wmma::fragment<wmma::matrix_a, 16, 16, 8, wmma::precision::tf32, wmma::row_major> af[4];
#pragma unroll
                    for (int i = 0; i < 4; i++) {
                        wmma::load_matrix_sync(af[i], hin + (size_t)(i * 16) * 1024 + k0, 1024);
#pragma unroll
                        for (int e = 0; e < af[i].num_elements; e++)
                            af[i].x[e] = wmma::__float_to_tf32(af[i].x[e]);
                        wmma::mma_sync(acc[i][0], af[i], bfr[0], acc[i][0]);
                        wmma::mma_sync(acc[i][1], af[i], bfr[1], acc[i][1]);
                    }
                }
#pragma unroll
                for (int i = 0; i < 4; i++)
#pragma unroll
                    for (int j = 0; j < 2; j++)
                        wmma::store_matrix_sync(&sP[warp * (64 * SPP) + (i * 16) * SPP + j * 16],
                                                acc[i][j], SPP, wmma::mem_row_major);
                __syncthreads();
            } else {
                // ---- sparse apply, MLP-optimized: warp w owns b in [8w,8w+8) --
                const int ph = (t - 1) % 3;
                const int b0 = warp << 3;
                int myc = (lane < 8) ? __ldcg(&g_lcnt[ph][b0 + lane]) : 0;
                int n[8];
                int nmax = 0;
#pragma unroll
                for (int bb = 0; bb < 8; bb++) {
                    n[bb] = __shfl_sync(0xffffffffu, myc, bb);
                    nmax = max(nmax, n[bb]);
                }
                float acc[8];
#pragma unroll
                for (int bb = 0; bb < 8; bb++)
                    acc[bb] = sAcc[(b0 + bb) * ACP + lane];

                for (int e = 0; e < nmax; ++e) {
#pragma unroll
                    for (int bb = 0; bb < 8; bb++) {
                        if (e < n[bb]) {
                            float2 E = __ldcg(&g_blist[ph][b0 + bb][e]);
                            acc[bb] += E.y * sW[__float_as_int(E.x) * SWP + lane];
                        }
                    }
                }
#pragma unroll
                for (int bb = 0; bb < 8; bb++)
                    sAcc[(b0 + bb) * ACP + lane] = acc[bb];
                __syncthreads();
            }
        }

        // ---- elementwise: gates, state, cummax, record emission ----
        float* __restrict__ hnew = g_hbuf[t & 1];
        float outv[2];
        bool emitted = false;
#pragma unroll
        for (int l = 0; l < 2; l++) {
            int e  = tid + l * THREADS;      // 0..511
            int b  = e >> 3, hh = e & 7;
            int h  = h0 + hh;

            float s0, s1, s2, s3;
            if (dense) {
                s0 = s1 = s2 = s3 = 0.f;
                if (t > 0) {
#pragma unroll
                    for (int w = 0; w < 8; w++) {
                        const float* p = &sP[w * (64 * SPP) + b * SPP];
                        s0 += p[hh];
                        s1 += p[8 + hh];
                        s2 += p[16 + hh];
                        s3 += p[24 + hh];
                    }
                }
                sAcc[b * ACP + hh]      = s0;
                sAcc[b * ACP + 8 + hh]  = s1;
                sAcc[b * ACP + 16 + hh] = s2;
                sAcc[b * ACP + 24 + hh] = s3;
            } else {
                s0 = sAcc[b * ACP + hh];
                s1 = sAcc[b * ACP + 8 + hh];
                s2 = sAcc[b * ACP + 16 + hh];
                s3 = sAcc[b * ACP + 24 + hh];
            }

            float gf = s0 + gx[l][0] + sBias[hh];
            float gi = s1 + gx[l][1] + sBias[8 + hh];
            float gc = s2 + gx[l][2] + sBias[16 + hh];
            float go = s3 + gx[l][3] + sBias[24 + hh];

            float Cn = sigf(gf) * creg[l] + sigf(gi) * tanhf(gc);
            creg[l] = Cn;
            float hv = sigf(go) * tanhf(Cn);
            outv[l] = hv;

            // record event for the sparse accumulator (consumed at t+1)
            if (t >= TD - 1 && t < SEQ - 1 && hv > hreg[l]) {
                float dlt = hv - hreg[l];
                int pos = atomicAdd(&g_lcnt[t % 3][b], 1);
                g_blist[t % 3][b][pos] = make_float2(__int_as_float(h), dlt);
                emitted = true;
            }
            float hm = (t == 0) ? hv : fmaxf(hreg[l], hv);
            hreg[l] = hm;

            // hmax buffer needed only while dense steps read it
            if (t < TD - 1) hnew[b * HID + h] = hm;

            if (t == SEQ - 1) {
                out[(size_t)b * SEQ * HID + (size_t)t * HID + h] = hv;
                out[(size_t)BSH + b * HID + h] = hm;                     // h_fin
                out[(size_t)BSH + BATCH * HID + b * HID + h] = Cn;       // C_fin
            }
        }

        if (t < SEQ - 1) {
            // release cross-CTA payloads (hmax for dense; records if emitted)
            if (dense || emitted) __threadfence();
            __syncthreads();
            if (tid == 0) atomicAdd(&g_bar[t], 1u);

            // ---- work hidden under the barrier wait ----
#pragma unroll
            for (int l = 0; l < 2; l++) {
                int e = tid + l * THREADS;
                int b = e >> 3, hh = e & 7;
                out[(size_t)b * SEQ * HID + (size_t)t * HID + h0 + hh] = outv[l];
            }
#pragma unroll
            for (int l = 0; l < 2; l++) {
                int e = tid + l * THREADS;
                int b = e >> 3, hh = e & 7;
                const float* gp = g_Gx + (size_t)((t + 1) * 64 + b) * G4 + h0 + hh;
#pragma unroll
                for (int g = 0; g < 4; g++) gx[l][g] = __ldcg(gp + g * 1024);
            }

            if (tid == 0) {
                volatile unsigned* p = &g_bar[t];
                while (*p < (unsigned)CTAS) __nanosleep(32);
                if (t + 1 < TD) __threadfence();   // L1 inval only while dense readers exist
            }
            __syncthreads();
        }
    }
}

extern "C" void kernel_launch(void* const* d_in, const int* in_sizes, int n_in,
                              void* d_out, int out_size) {
    const float* x  = (const float*)d_in[0];
    const float* Wf = (const float*)d_in[1];
    const float* bf = (const float*)d_in[2];
    const float* Wi = (const float*)d_in[3];
    const float* bi = (const float*)d_in[4];
    const float* Wc = (const float*)d_in[5];
    const float* bc = (const float*)d_in[6];
    const float* Wo = (const float*)d_in[7];
    const float* bo = (const float*)d_in[8];
    float* out = (float*)d_out;

    static const size_t SMEM_L =
        (1024 * SWP + 8 * 64 * SPP + 64 * ACP) * sizeof(float);          // 217,344 B
    static const size_t SMEM_G =
        (2 * 128 * SAP + 2 * 32 * SBP) * sizeof(float);                  // 70,656 B
    cudaFuncSetAttribute(k_lstm,   cudaFuncAttributeMaxDynamicSharedMemorySize, (int)SMEM_L);
    cudaFuncSetAttribute(k_gemm_x, cudaFuncAttributeMaxDynamicSharedMemorySize, (int)SMEM_G);

    k_init<<<1, 512>>>();
    k_gemm_x<<<dim3(32, 256), 256, SMEM_G>>>(x, Wf, Wi, Wc, Wo);
    k_lstm<<<CTAS, THREADS, SMEM_L>>>(Wf, Wi, Wc, Wo, bf, bi, bc, bo, out);
}